// round 2
// baseline (speedup 1.0000x reference)
#include <cuda_runtime.h>
#include <math.h>

#define S_LEN  2048
#define BATCH  2
#define DMODEL 1024
#define NHEADS 16
#define DK     64
#define MTOT   (BATCH * S_LEN)   // 4096

// ---------------- scratch (static device allocations; no cudaMalloc) -----
__device__ float  g_q[(size_t)BATCH * S_LEN * DMODEL];
__device__ float  g_k[(size_t)BATCH * S_LEN * DMODEL];
__device__ float  g_v[(size_t)BATCH * S_LEN * DMODEL];
__device__ float  g_att[(size_t)BATCH * S_LEN * DMODEL];
__device__ float2 g_rope[S_LEN * (DK / 2)];   // [s][i] cos/sin

// ========================================================================
// GEMM:  C[m,n] = sum_k A[m,k] * B[n,k]   (A: MTOTxK row-major, B: NxK)
// M=4096, N=1024, K=1024 fixed. BM=BN=128, BK=16, 256 thr, 8x8 microtile.
// ========================================================================
__global__ __launch_bounds__(256) void sgemm_nt(const float* __restrict__ A,
                                                const float* __restrict__ B,
                                                float* __restrict__ C) {
    constexpr int LD = 132;                 // padded smem stride
    __shared__ float As[16 * LD];           // [k][m]
    __shared__ float Bs[16 * LD];           // [k][n]

    const int bn  = blockIdx.x * 128;
    const int bm  = blockIdx.y * 128;
    const int tid = threadIdx.x;
    const int tx  = tid & 15;
    const int ty  = tid >> 4;

    float acc[8][8];
#pragma unroll
    for (int i = 0; i < 8; i++)
#pragma unroll
        for (int j = 0; j < 8; j++) acc[i][j] = 0.f;

    const float* Ap = A + (size_t)bm * DMODEL;
    const float* Bp = B + (size_t)bn * DMODEL;

    for (int kk = 0; kk < DMODEL; kk += 16) {
#pragma unroll
        for (int q = 0; q < 2; q++) {
            int f   = tid + q * 256;        // 0..511 float4s
            int row = f >> 2;               // 0..127
            int kg  = f & 3;                // 0..3 (16B group within BK)
            float4 av = *(const float4*)(Ap + (size_t)row * DMODEL + kk + kg * 4);
            As[(kg * 4 + 0) * LD + row] = av.x;
            As[(kg * 4 + 1) * LD + row] = av.y;
            As[(kg * 4 + 2) * LD + row] = av.z;
            As[(kg * 4 + 3) * LD + row] = av.w;
            float4 bv = *(const float4*)(Bp + (size_t)row * DMODEL + kk + kg * 4);
            Bs[(kg * 4 + 0) * LD + row] = bv.x;
            Bs[(kg * 4 + 1) * LD + row] = bv.y;
            Bs[(kg * 4 + 2) * LD + row] = bv.z;
            Bs[(kg * 4 + 3) * LD + row] = bv.w;
        }
        __syncthreads();

#pragma unroll
        for (int k = 0; k < 16; k++) {
            float a[8], b[8];
            *(float4*)(a)     = *(const float4*)&As[k * LD + ty * 4];
            *(float4*)(a + 4) = *(const float4*)&As[k * LD + 64 + ty * 4];
            *(float4*)(b)     = *(const float4*)&Bs[k * LD + tx * 4];
            *(float4*)(b + 4) = *(const float4*)&Bs[k * LD + 64 + tx * 4];
#pragma unroll
            for (int i = 0; i < 8; i++)
#pragma unroll
                for (int j = 0; j < 8; j++) acc[i][j] += a[i] * b[j];
        }
        __syncthreads();
    }

#pragma unroll
    for (int ar = 0; ar < 2; ar++)
#pragma unroll
        for (int i = 0; i < 4; i++) {
            int row = bm + ar * 64 + ty * 4 + i;
#pragma unroll
            for (int bc = 0; bc < 2; bc++) {
                float4 v = make_float4(acc[ar * 4 + i][bc * 4 + 0],
                                       acc[ar * 4 + i][bc * 4 + 1],
                                       acc[ar * 4 + i][bc * 4 + 2],
                                       acc[ar * 4 + i][bc * 4 + 3]);
                *(float4*)(C + (size_t)row * DMODEL + bn + bc * 64 + tx * 4) = v;
            }
        }
}

// ========================================================================
// RoPE table: cos/sin of (float)(s) * freq_i, trig evaluated in double of
// the fp32-rounded angle to track the reference numerics.
// ========================================================================
__global__ void rope_table_kernel() {
    int idx = blockIdx.x * blockDim.x + threadIdx.x;   // 65536
    if (idx >= S_LEN * (DK / 2)) return;
    int s = idx >> 5;
    int i = idx & 31;
    float freq = 1.0f / powf(10000.0f, (float)(2 * i) / 64.0f);
    float ang  = (float)s * freq;                      // fp32 like the reference
    double a   = (double)ang;
    g_rope[idx] = make_float2((float)cos(a), (float)sin(a));
}

// Apply RoPE in place. Pairs are adjacent (even,odd) elements; head
// boundaries (64) align with the pair structure, so pair p in the 1024-wide
// row has rotation index i = p % 32.
__global__ void rope_apply_kernel(float* __restrict__ t) {
    int idx = blockIdx.x * blockDim.x + threadIdx.x;   // BATCH*S_LEN*512
    if (idx >= BATCH * S_LEN * (DMODEL / 2)) return;
    int row = idx >> 9;              // b*S + s
    int pp  = idx & 511;
    int s   = row & (S_LEN - 1);
    float2 cs = g_rope[(s << 5) + (pp & 31)];
    float2 v  = ((const float2*)t)[idx];
    float2 r;
    r.x = v.x * cs.x - v.y * cs.y;
    r.y = v.x * cs.y + v.y * cs.x;
    ((float2*)t)[idx] = r;
}

// ========================================================================
// Flash attention, fp32, causal. BM=BN=64, Dk=64, 256 threads.
// Q/K transposed in smem ([d][m], stride 64) via column-slab loads so both
// the transpose stores and the float4 compute reads are conflict-free.
// ========================================================================
__global__ __launch_bounds__(256) void flash_attn(const float* __restrict__ Qg,
                                                  const float* __restrict__ Kg,
                                                  const float* __restrict__ Vg,
                                                  float* __restrict__ Og) {
    extern __shared__ float sm[];
    float* Qt = sm;                  // [64][64]  d-major
    float* Kt = sm + 4096;           // [64][64]  d-major
    float* Vs = sm + 8192;           // [64][64]  n-major
    float* Ps = sm + 12288;          // [64][68]  m-major, padded

    const int qt  = gridDim.x - 1 - blockIdx.x;   // long blocks first
    const int h   = blockIdx.y;
    const int b   = blockIdx.z;
    const int tid = threadIdx.x;
    const int tx  = tid & 15;
    const int ty  = tid >> 4;
    const size_t base = ((size_t)b * S_LEN) * DMODEL + h * DK;
    const int q0 = qt * 64;

    // load Q transposed
#pragma unroll
    for (int p = 0; p < 4; p++) {
        int f = tid + p * 256;
        int m = f & 63, kg = f >> 6;
        float4 v = *(const float4*)(Qg + base + (size_t)(q0 + m) * DMODEL + kg * 4);
        Qt[(kg * 4 + 0) * 64 + m] = v.x;
        Qt[(kg * 4 + 1) * 64 + m] = v.y;
        Qt[(kg * 4 + 2) * 64 + m] = v.z;
        Qt[(kg * 4 + 3) * 64 + m] = v.w;
    }

    float o[4][4];
    float m_i[4], l_i[4];
#pragma unroll
    for (int i = 0; i < 4; i++) {
        m_i[i] = -INFINITY;
        l_i[i] = 0.f;
#pragma unroll
        for (int j = 0; j < 4; j++) o[i][j] = 0.f;
    }
    const float scale = 0.125f;   // 1/sqrt(64)

    for (int kt = 0; kt <= qt; kt++) {
        const int k0 = kt * 64;
        __syncthreads();   // prior PV reads of Vs/Ps done
#pragma unroll
        for (int p = 0; p < 4; p++) {
            int f = tid + p * 256;
            int n = f & 63, kg = f >> 6;
            float4 kv = *(const float4*)(Kg + base + (size_t)(k0 + n) * DMODEL + kg * 4);
            Kt[(kg * 4 + 0) * 64 + n] = kv.x;
            Kt[(kg * 4 + 1) * 64 + n] = kv.y;
            Kt[(kg * 4 + 2) * 64 + n] = kv.z;
            Kt[(kg * 4 + 3) * 64 + n] = kv.w;
            int n2 = f >> 4, c = (f & 15) * 4;
            *(float4*)&Vs[n2 * 64 + c] =
                *(const float4*)(Vg + base + (size_t)(k0 + n2) * DMODEL + c);
        }
        __syncthreads();

        float s[4][4];
#pragma unroll
        for (int i = 0; i < 4; i++)
#pragma unroll
            for (int j = 0; j < 4; j++) s[i][j] = 0.f;

#pragma unroll 4
        for (int d = 0; d < 64; d++) {
            float qa[4], kb[4];
            *(float4*)qa = *(const float4*)&Qt[d * 64 + ty * 4];
            *(float4*)kb = *(const float4*)&Kt[d * 64 + tx * 4];
#pragma unroll
            for (int i = 0; i < 4; i++)
#pragma unroll
                for (int j = 0; j < 4; j++) s[i][j] += qa[i] * kb[j];
        }

        const bool diag = (kt == qt);
#pragma unroll
        for (int i = 0; i < 4; i++) {
#pragma unroll
            for (int j = 0; j < 4; j++) {
                s[i][j] *= scale;
                if (diag && (k0 + tx * 4 + j > q0 + ty * 4 + i)) s[i][j] = -INFINITY;
            }
            float lm = fmaxf(fmaxf(s[i][0], s[i][1]), fmaxf(s[i][2], s[i][3]));
#pragma unroll
            for (int off = 8; off; off >>= 1)
                lm = fmaxf(lm, __shfl_xor_sync(0xffffffffu, lm, off, 16));
            float newm = fmaxf(m_i[i], lm);
            float corr = expf(m_i[i] - newm);
            float pr[4];
            float rs = 0.f;
#pragma unroll
            for (int j = 0; j < 4; j++) {
                pr[j] = expf(s[i][j] - newm);
                rs += pr[j];
            }
#pragma unroll
            for (int off = 8; off; off >>= 1)
                rs += __shfl_xor_sync(0xffffffffu, rs, off, 16);
            l_i[i] = l_i[i] * corr + rs;
            m_i[i] = newm;
#pragma unroll
            for (int j = 0; j < 4; j++) o[i][j] *= corr;
            *(float4*)&Ps[(ty * 4 + i) * 68 + tx * 4] =
                make_float4(pr[0], pr[1], pr[2], pr[3]);
        }
        __syncthreads();

#pragma unroll 2
        for (int n4 = 0; n4 < 64; n4 += 4) {
            float pv[4][4];
#pragma unroll
            for (int i = 0; i < 4; i++)
                *(float4*)pv[i] = *(const float4*)&Ps[(ty * 4 + i) * 68 + n4];
#pragma unroll
            for (int t = 0; t < 4; t++) {
                float vv[4];
                *(float4*)vv = *(const float4*)&Vs[(n4 + t) * 64 + tx * 4];
#pragma unroll
                for (int i = 0; i < 4; i++)
#pragma unroll
                    for (int j = 0; j < 4; j++) o[i][j] += pv[i][t] * vv[j];
            }
        }
    }

#pragma unroll
    for (int i = 0; i < 4; i++) {
        float inv = 1.0f / l_i[i];
        float4 r = make_float4(o[i][0] * inv, o[i][1] * inv,
                               o[i][2] * inv, o[i][3] * inv);
        *(float4*)(Og + base + (size_t)(q0 + ty * 4 + i) * DMODEL + tx * 4) = r;
    }
}

// ========================================================================
extern "C" void kernel_launch(void* const* d_in, const int* in_sizes, int n_in,
                              void* d_out, int out_size) {
    (void)in_sizes; (void)n_in; (void)out_size;
    const float* x  = (const float*)d_in[0];
    const float* Wq = (const float*)d_in[1];
    const float* Wk = (const float*)d_in[2];
    const float* Wv = (const float*)d_in[3];
    const float* Wo = (const float*)d_in[4];
    float* out = (float*)d_out;

    float *q, *k, *v, *att;
    cudaGetSymbolAddress((void**)&q,   g_q);
    cudaGetSymbolAddress((void**)&k,   g_k);
    cudaGetSymbolAddress((void**)&v,   g_v);
    cudaGetSymbolAddress((void**)&att, g_att);

    dim3 gg(DMODEL / 128, MTOT / 128);   // (8, 32)
    sgemm_nt<<<gg, 256>>>(x, Wq, q);
    sgemm_nt<<<gg, 256>>>(x, Wk, k);
    sgemm_nt<<<gg, 256>>>(x, Wv, v);

    rope_table_kernel<<<(S_LEN * (DK / 2) + 255) / 256, 256>>>();
    rope_apply_kernel<<<(BATCH * S_LEN * (DMODEL / 2) + 255) / 256, 256>>>(q);
    rope_apply_kernel<<<(BATCH * S_LEN * (DMODEL / 2) + 255) / 256, 256>>>(k);

    cudaFuncSetAttribute(flash_attn,
                         cudaFuncAttributeMaxDynamicSharedMemorySize, 66560);
    flash_attn<<<dim3(S_LEN / 64, NHEADS, BATCH), 256, 66560>>>(q, k, v, att);

    sgemm_nt<<<gg, 256>>>(att, Wo, out);
}